// round 8
// baseline (speedup 1.0000x reference)
#include <cuda_runtime.h>
#include <cuda_fp16.h>
#include <cstdint>

// Problem constants
#define NL   8
#define NH   512
#define NK   16
#define NIN  512
#define NB   8192
#define NR   16        // batch rows per block (8 row-pairs, half2 packed)
#define NRP  8
#define WSTORE (NIN + (NL-1)*NH)   // 4096 stored columns
#define VST  8         // column stride in half2 words: col c -> bank octet (c & 3)

#define STG_ROW   144                  // staged row stride bytes (128 data + 16 pad)
#define STG_WARP  (16*STG_ROW)         // 2304 B per warp
#define SMEM_BYTES (WSTORE*VST*4 + 32*STG_WARP)   // 131072 + 73728 = 204800

// combined idx|w, warp-blocked: [l][warp][row(=p*8+j)][16 idx | 16 w]
__device__ __align__(16) int g_cmb[NL*32*512];

// ---------------- scheduling pre-kernel ----------------
// One thread per 8-h group (l, p, warp). Permutes each h's 16 (idx,w) pairs so
// step t uses 8 columns whose (idx mod 4) residues cover each class <= 2x
// -> LDS.64 gather hits every bank at most twice = the 256B floor (2 wavefronts).
__global__ void sched_kernel(const int* __restrict__ link_idx,
                             const float* __restrict__ weights)
{
    int q = blockIdx.x * blockDim.x + threadIdx.x;   // 0..511
    int l = q >> 6, rem = q & 63;
    int p = rem >> 5, w = rem & 31;
    int h0 = p*256 + w*8;

    // bulk-load this group's 8 rows x 16 (idx, w) contiguously (no in-loop LDG)
    int   li[128];
    float lw[128];
    {
        const int4*   gi = (const int4*)  (link_idx + (l*NH + h0)*NK);
        const float4* gw = (const float4*)(weights  + (l*NH + h0)*NK);
        #pragma unroll
        for (int m = 0; m < 32; m++) {
            *(int4*)  &li[m*4] = gi[m];
            *(float4*)&lw[m*4] = gw[m];
        }
    }

    unsigned msk[8][4];
    #pragma unroll
    for (int j = 0; j < 8; j++) {
        msk[j][0] = msk[j][1] = msk[j][2] = msk[j][3] = 0u;
        #pragma unroll
        for (int k = 0; k < 16; k++)
            msk[j][li[j*16 + k] & 3] |= 1u << k;
    }

    const int dstbase = (l*32 + w)*512 + p*8*32;
    for (int t = 0; t < 16; t++) {
        int used[4] = {0, 0, 0, 0};
        #pragma unroll
        for (int j = 0; j < 8; j++) {
            int bestr = 0, bests = -1;
            #pragma unroll
            for (int r = 0; r < 4; r++) {
                int c = __popc(msk[j][r]);
                int s = (c == 0) ? -1 : c + ((used[r] < 2) ? 16 : 0);
                if (s > bests) { bests = s; bestr = r; }
            }
            used[bestr]++;
            int kk = __ffs(msk[j][bestr]) - 1;
            msk[j][bestr] &= msk[j][bestr] - 1u;

            g_cmb[dstbase + j*32 + t]      = li[j*16 + kk];
            g_cmb[dstbase + j*32 + 16 + t] = __float_as_int(lw[j*16 + kk]);
        }
    }
}

__device__ __forceinline__ float fast_sigmoid(float z) {
    float t;
    asm("tanh.approx.f32 %0, %1;" : "=f"(t) : "f"(0.5f * z));
    return fmaf(0.5f, t, 0.5f);
}

// ---------------- main fused kernel ----------------
__global__ __launch_bounds__(1024, 1)
void ffn_kernel(const float* __restrict__ x,
                const float* __restrict__ bias,
                float*       __restrict__ out)
{
    extern __shared__ __half2 smem2[];
    __half2* vals2 = smem2;                               // [4096 cols][8 rp], stride 8
    char*    stage = (char*)(smem2 + WSTORE * VST);       // 32 warp-private 2304B blocks

    unsigned int stage_u32 =
        (unsigned int)__cvta_generic_to_shared(stage);

    const int tid  = threadIdx.x;
    const int lane = tid & 31;
    const int warp = tid >> 5;
    const int hj   = lane >> 2;         // 0..7  (h within warp's group of 8)
    const int g    = lane & 3;          // rp-pair group: covers row-pairs 2g, 2g+1
    const int r0   = blockIdx.x * NR;

    // ---- x tile: (c, pp) mapping -> conflict-free STS ----
    #pragma unroll
    for (int i = tid; i < NRP * NIN; i += 1024) {         // 4096 half2
        int c  = i >> 3;
        int pp = i & 7;
        float a = x[(long)(r0 + 2*pp    ) * NIN + c];
        float b = x[(long)(r0 + 2*pp + 1) * NIN + c];
        vals2[c * VST + pp] = __floats2half2_rn(a, b);
    }

    int width = NIN;
    #pragma unroll 1
    for (int l = 0; l < NL; l++) {
        // ---- warp-private staging of this layer's combined idx|w (cp.async) ----
        {
            const int4* src = (const int4*)(g_cmb + (size_t)(l*32 + warp) * 512);
            const unsigned int dstbase = stage_u32 + warp * STG_WARP;
            const int a = lane >> 3, b = lane & 7;
            #pragma unroll
            for (int c = 0; c < 4; c++) {
                int r = c*4 + a;
                unsigned int dst = dstbase + r * STG_ROW + b * 16;
                const int4* s = src + (c*32 + lane);
                asm volatile("cp.async.ca.shared.global [%0], [%1], 16;"
                             :: "r"(dst), "l"(s));
            }
            asm volatile("cp.async.commit_group;" ::: "memory");
        }

        __syncthreads();   // previous layer's values visible
        asm volatile("cp.async.wait_group 0;" ::: "memory");
        __syncwarp();      // staged chunks visible warp-wide

        const float* brow = bias + l * NH;
        const bool last = (l == NL - 1);
        const char* wblk = stage + warp * STG_WARP;

        #pragma unroll
        for (int p = 0; p < 2; p++) {
            const int h = p * 256 + warp * 8 + hj;
            const char* rowp = wblk + (p*8 + hj) * STG_ROW;

            const int4*   si = (const int4*)  rowp;
            const float4* sw = (const float4*)(rowp + 64);

            float b0 = __ldg(brow + h);
            float a0x = b0, a0y = b0, a1x = b0, a1y = b0;

            // each lane: LDS.64 -> 2 half2 (4 batch rows) of one scheduled column
#define GATHER(idx, wv) { \
    float2 qv = *(const float2*)(vals2 + (idx) * VST + 2*g); \
    float2 f0 = __half22float2(((const __half2*)&qv)[0]); \
    float2 f1 = __half22float2(((const __half2*)&qv)[1]); \
    a0x = fmaf(f0.x, (wv), a0x); a0y = fmaf(f0.y, (wv), a0y); \
    a1x = fmaf(f1.x, (wv), a1x); a1y = fmaf(f1.y, (wv), a1y); }

            {   // chunk 1: k = 0..7 (keeps register pressure under the 64-reg cap)
                int4   i0 = si[0], i1 = si[1];
                float4 w0 = sw[0], w1 = sw[1];
                GATHER(i0.x, w0.x); GATHER(i0.y, w0.y);
                GATHER(i0.z, w0.z); GATHER(i0.w, w0.w);
                GATHER(i1.x, w1.x); GATHER(i1.y, w1.y);
                GATHER(i1.z, w1.z); GATHER(i1.w, w1.w);
            }
            {   // chunk 2: k = 8..15
                int4   i2 = si[2], i3 = si[3];
                float4 w2 = sw[2], w3 = sw[3];
                GATHER(i2.x, w2.x); GATHER(i2.y, w2.y);
                GATHER(i2.z, w2.z); GATHER(i2.w, w2.w);
                GATHER(i3.x, w3.x); GATHER(i3.y, w3.y);
                GATHER(i3.z, w3.z); GATHER(i3.w, w3.w);
            }
#undef GATHER

            float s0x = fast_sigmoid(a0x);
            float s0y = fast_sigmoid(a0y);
            float s1x = fast_sigmoid(a1x);
            float s1y = fast_sigmoid(a1y);

            if (!last) {
                // STS.64: 8 hj cover each octet 2x -> 2 phases (= 256B floor)
                __half2 o0 = __floats2half2_rn(s0x, s0y);
                __half2 o1 = __floats2half2_rn(s1x, s1y);
                float2 st;
                ((__half2*)&st)[0] = o0;
                ((__half2*)&st)[1] = o1;
                *(float2*)(vals2 + (width + h) * VST + 2*g) = st;
            } else {
                out[(long)(r0 + 4*g    ) * NH + h] = s0x;
                out[(long)(r0 + 4*g + 1) * NH + h] = s0y;
                out[(long)(r0 + 4*g + 2) * NH + h] = s1x;
                out[(long)(r0 + 4*g + 3) * NH + h] = s1y;
            }
        }
        width += NH;
    }
}

extern "C" void kernel_launch(void* const* d_in, const int* in_sizes, int n_in,
                              void* d_out, int out_size)
{
    const float* x        = (const float*)d_in[0];   // (8192, 512) f32
    const int*   link_idx = (const int*)d_in[1];     // (8, 512, 16) i32
    const float* weights  = (const float*)d_in[2];   // (8, 512, 16) f32
    const float* bias     = (const float*)d_in[3];   // (8, 512) f32
    float*       out      = (float*)d_out;           // (8192, 512) f32

    cudaFuncSetAttribute(ffn_kernel,
                         cudaFuncAttributeMaxDynamicSharedMemorySize, SMEM_BYTES);

    sched_kernel<<<16, 32>>>(link_idx, weights);
    ffn_kernel<<<NB / NR, 1024, SMEM_BYTES>>>(x, bias, out);
}

// round 9
// speedup vs baseline: 1.0724x; 1.0724x over previous
#include <cuda_runtime.h>
#include <cuda_fp16.h>
#include <cstdint>

// Problem constants
#define NL   8
#define NH   512
#define NK   16
#define NIN  512
#define NB   8192
#define NR   16        // batch rows per block (8 row-pairs, half2 packed)
#define NRP  8
#define WSTORE (NIN + (NL-1)*NH)   // 4096 stored columns
#define VST  8         // column stride in half2 words: col c -> bank octet (c & 3)

#define STG_ROW   144                  // staged row stride bytes (128 data + 16 pad)
#define STG_WARP  (16*STG_ROW)         // 2304 B per warp
#define SMEM_BYTES (WSTORE*VST*4 + 32*STG_WARP)   // 131072 + 73728 = 204800

#define SCHED_SMEM (NH*NK*4*2)         // 65536 B: layer's idx + weights

// combined idx|w, warp-blocked: [l][warp][row(=p*4+j)][16 idx | 16 w]
__device__ __align__(16) int g_cmb[NL*32*512];

// ---------------- scheduling pre-kernel ----------------
// One block per layer; the layer's idx/w staged into SMEM (coalesced), then one
// thread per h-quad runs the bitmask greedy: step t uses 4 columns with
// pairwise-distinct (idx mod 4) -> gather = 1 smem wavefront in ffn_kernel.
__global__ void sched_kernel(const int* __restrict__ link_idx,
                             const float* __restrict__ weights)
{
    extern __shared__ int ssch[];
    int*   sidx = ssch;              // [NH*NK]
    float* swt  = (float*)(ssch + NH*NK);

    const int tid = threadIdx.x;     // 0..127
    const int l   = blockIdx.x;      // 0..7

    // coalesced bulk load of this layer's tables (2048 int4 each)
    {
        const int4*   gi = (const int4*)(link_idx + l * NH * NK);
        const int4*   gw = (const int4*)(weights  + l * NH * NK);
        int4* si = (int4*)sidx;
        int4* sw = (int4*)swt;
        #pragma unroll
        for (int i = tid; i < (NH*NK)/4; i += 128) {
            si[i] = gi[i];
            sw[i] = gw[i];
        }
    }
    __syncthreads();

    const int qq = tid;              // h-quad id within layer
    const int p  = qq >> 5, w = qq & 31;
    const int h0 = qq * 4;           // == p*128 + w*4

    // position bitmasks per (j, residue)
    unsigned m[4][4];
    #pragma unroll
    for (int j = 0; j < 4; j++) {
        m[j][0] = m[j][1] = m[j][2] = m[j][3] = 0u;
        const int* row = sidx + (h0 + j) * NK;
        #pragma unroll
        for (int k = 0; k < 16; k++)
            m[j][row[k] & 3] |= 1u << k;
    }

    for (int t = 0; t < 16; t++) {
        unsigned claimed = 0;
        #pragma unroll
        for (int j = 0; j < 4; j++) {
            int bestr = 0, bests = -1;
            #pragma unroll
            for (int r = 0; r < 4; r++) {
                int c = __popc(m[j][r]);
                int s = (c == 0) ? -1 : c + (((claimed >> r) & 1u) ? 0 : 16);
                if (s > bests) { bests = s; bestr = r; }
            }
            claimed |= 1u << bestr;
            int kk = __ffs(m[j][bestr]) - 1;
            m[j][bestr] &= m[j][bestr] - 1u;

            const int src = (h0 + j) * NK + kk;
            const int dst = (l*32 + w)*512 + (p*4 + j)*32;
            g_cmb[dst + t]      = sidx[src];
            g_cmb[dst + 16 + t] = __float_as_int(swt[src]);
        }
    }
}

__device__ __forceinline__ float fast_sigmoid(float z) {
    float t;
    asm("tanh.approx.f32 %0, %1;" : "=f"(t) : "f"(0.5f * z));
    return fmaf(0.5f, t, 0.5f);
}

// ---------------- main fused kernel (identical to R7's 120.8us version) ----------------
__global__ __launch_bounds__(1024, 1)
void ffn_kernel(const float* __restrict__ x,
                const float* __restrict__ bias,
                float*       __restrict__ out)
{
    extern __shared__ __half2 smem2[];
    __half2* vals2 = smem2;                               // [4096 cols][8 rp], stride 8
    char*    stage = (char*)(smem2 + WSTORE * VST);       // 32 warp-private 2304B blocks

    unsigned int stage_u32 =
        (unsigned int)__cvta_generic_to_shared(stage);

    const int tid  = threadIdx.x;
    const int lane = tid & 31;
    const int warp = tid >> 5;
    const int rp   = lane & 7;          // row-pair 0..7
    const int hsub = lane >> 3;         // 0..3
    const int r0   = blockIdx.x * NR;

    // ---- x tile: (c, pp) mapping -> conflict-free STS ----
    #pragma unroll
    for (int i = tid; i < NRP * NIN; i += 1024) {         // 4096 half2
        int c  = i >> 3;
        int pp = i & 7;
        float a = x[(long)(r0 + 2*pp    ) * NIN + c];
        float b = x[(long)(r0 + 2*pp + 1) * NIN + c];
        vals2[c * VST + pp] = __floats2half2_rn(a, b);
    }

    int width = NIN;
    #pragma unroll 1
    for (int l = 0; l < NL; l++) {
        // ---- warp-private staging of this layer's combined idx|w (cp.async) ----
        {
            const int4* src = (const int4*)(g_cmb + (size_t)(l*32 + warp) * 512);
            const unsigned int dstbase = stage_u32 + warp * STG_WARP;
            const int a = lane >> 3, b = lane & 7;
            #pragma unroll
            for (int c = 0; c < 4; c++) {
                int r = c*4 + a;
                unsigned int dst = dstbase + r * STG_ROW + b * 16;
                const int4* s = src + (c*32 + lane);
                asm volatile("cp.async.ca.shared.global [%0], [%1], 16;"
                             :: "r"(dst), "l"(s));
            }
            asm volatile("cp.async.commit_group;" ::: "memory");
        }

        __syncthreads();   // values from previous layer (or x tile) visible
        asm volatile("cp.async.wait_group 0;" ::: "memory");
        __syncwarp();      // staged chunks visible warp-wide

        const float* brow = bias + l * NH;
        const bool last = (l == NL - 1);
        const char* wblk = stage + warp * STG_WARP;

        #pragma unroll
        for (int p = 0; p < 4; p++) {
            const int h = p * 128 + warp * 4 + hsub;
            const char* rowp = wblk + (p*4 + hsub) * STG_ROW;

            // 4 distinct addresses per warp, disjoint bank quads -> 1 wf each
            const int4*   si = (const int4*)  rowp;
            const float4* sw = (const float4*)(rowp + 64);
            int4   i0 = si[0], i1 = si[1], i2 = si[2], i3 = si[3];
            float4 w0 = sw[0], w1 = sw[1], w2 = sw[2], w3 = sw[3];

            float b0 = __ldg(brow + h);
            float ax0 = b0,   ay0 = b0;
            float ax1 = 0.0f, ay1 = 0.0f;

            // scheduled gathers: 4 cols with distinct (idx & 3) -> 1 wavefront
#define GATHER0(idx, w) { float2 f = __half22float2(vals2[(idx) * VST + rp]); \
                          ax0 = fmaf(f.x, (w), ax0); ay0 = fmaf(f.y, (w), ay0); }
#define GATHER1(idx, w) { float2 f = __half22float2(vals2[(idx) * VST + rp]); \
                          ax1 = fmaf(f.x, (w), ax1); ay1 = fmaf(f.y, (w), ay1); }
            GATHER0(i0.x, w0.x); GATHER1(i0.y, w0.y);
            GATHER0(i0.z, w0.z); GATHER1(i0.w, w0.w);
            GATHER0(i1.x, w1.x); GATHER1(i1.y, w1.y);
            GATHER0(i1.z, w1.z); GATHER1(i1.w, w1.w);
            GATHER0(i2.x, w2.x); GATHER1(i2.y, w2.y);
            GATHER0(i2.z, w2.z); GATHER1(i2.w, w2.w);
            GATHER0(i3.x, w3.x); GATHER1(i3.y, w3.y);
            GATHER0(i3.z, w3.z); GATHER1(i3.w, w3.w);
#undef GATHER0
#undef GATHER1

            float ox = fast_sigmoid(ax0 + ax1);
            float oy = fast_sigmoid(ay0 + ay1);

            if (!last) {
                // h mod 4 = hsub -> distinct octets x 8 rp -> conflict-free store
                vals2[(width + h) * VST + rp] = __floats2half2_rn(ox, oy);
            } else {
                out[(long)(r0 + 2*rp    ) * NH + h] = ox;
                out[(long)(r0 + 2*rp + 1) * NH + h] = oy;
            }
        }
        width += NH;
    }
}

extern "C" void kernel_launch(void* const* d_in, const int* in_sizes, int n_in,
                              void* d_out, int out_size)
{
    const float* x        = (const float*)d_in[0];   // (8192, 512) f32
    const int*   link_idx = (const int*)d_in[1];     // (8, 512, 16) i32
    const float* weights  = (const float*)d_in[2];   // (8, 512, 16) f32
    const float* bias     = (const float*)d_in[3];   // (8, 512) f32
    float*       out      = (float*)d_out;           // (8192, 512) f32

    cudaFuncSetAttribute(ffn_kernel,
                         cudaFuncAttributeMaxDynamicSharedMemorySize, SMEM_BYTES);
    cudaFuncSetAttribute(sched_kernel,
                         cudaFuncAttributeMaxDynamicSharedMemorySize, SCHED_SMEM);

    sched_kernel<<<NL, 128, SCHED_SMEM>>>(link_idx, weights);
    ffn_kernel<<<NB / NR, 1024, SMEM_BYTES>>>(x, bias, out);
}

// round 10
// speedup vs baseline: 1.1732x; 1.0940x over previous
#include <cuda_runtime.h>
#include <cuda_fp16.h>
#include <cstdint>

// Problem constants
#define NL   8
#define NH   512
#define NK   16
#define NIN  512
#define NB   8192
#define NR   16        // batch rows per block (8 row-pairs, half2 packed)
#define NRP  8
#define WSTORE (NIN + (NL-1)*NH)   // 4096 stored columns
#define VST  8         // column stride in half2 words: col c -> bank octet (c & 3)

#define STG_ROW   144                  // staged row stride bytes (128 data + 16 pad)
#define STG_WARP  (16*STG_ROW)         // 2304 B per warp
#define BIAS_OFF  (32*STG_WARP)        // bias staging after the idx|w blocks
#define SMEM_BYTES (WSTORE*VST*4 + 32*STG_WARP + 32*64)  // 131072+73728+2048 = 206848

// combined idx|w, warp-blocked: [l][warp][row(=p*4+j)][16 idx | 16 w]
__device__ __align__(16) int g_cmb[NL*32*512];
// per-warp bias table: [l][warp][16]  (slot p*4+j = bias for h = p*128 + warp*4 + j)
__device__ __align__(16) float g_cbias[NL*32*16];

// ---------------- scheduling pre-kernel (branchless, register-only) ----------------
// 32 blocks x 32 threads; block stages its 16KB idx/w slice in SMEM, each thread
// permutes one h-quad so step t uses 4 columns with pairwise-distinct (idx mod 4)
// -> each ffn gather = 1 smem wavefront. No dynamically-indexed register arrays.
__global__ void sched_kernel(const int* __restrict__ link_idx,
                             const float* __restrict__ weights,
                             const float* __restrict__ bias)
{
    __shared__ int sidx_s[128*16];
    __shared__ int swt_s [128*16];

    const int tid = threadIdx.x;                 // 0..31
    const int bid = blockIdx.x;                  // 0..31
    const int q   = bid * 32 + tid;              // quad 0..1023
    const int l   = q >> 7;
    const int qq  = q & 127;
    const int p   = qq >> 5, w = qq & 31;

    // stage this block's 128 h-rows of idx and w (coalesced)
    {
        const int base = (l * NH + (bid & 3) * 128) * NK;   // 2048 ints per table
        const int4* gi = (const int4*)(link_idx + base);
        const int4* gw = (const int4*)((const int*)weights + base);
        #pragma unroll
        for (int i = tid; i < 512; i += 32) {
            ((int4*)sidx_s)[i] = gi[i];
            ((int4*)swt_s)[i]  = gw[i];
        }
    }
    __syncthreads();

    const int rowb = tid * 4;                    // local h-row base for this quad

    // per-j residue masks as named registers
    unsigned m00=0,m01=0,m02=0,m03=0, m10=0,m11=0,m12=0,m13=0;
    unsigned m20=0,m21=0,m22=0,m23=0, m30=0,m31=0,m32=0,m33=0;
#define BUILD(J, A, B, C, D) { \
    const int* row = sidx_s + (rowb + J) * 16; \
    _Pragma("unroll") for (int k = 0; k < 16; k++) { \
        int rr = row[k] & 3; unsigned bit = 1u << k; \
        A |= (rr == 0) ? bit : 0u; B |= (rr == 1) ? bit : 0u; \
        C |= (rr == 2) ? bit : 0u; D |= (rr == 3) ? bit : 0u; } }
    BUILD(0, m00,m01,m02,m03) BUILD(1, m10,m11,m12,m13)
    BUILD(2, m20,m21,m22,m23) BUILD(3, m30,m31,m32,m33)
#undef BUILD

    const int dbase = (l*32 + w)*512 + p*128;    // g_cmb base for this quad

    for (int t = 0; t < 16; t++) {
        unsigned claimed = 0;
#define STEP(J, A, B, C, D) { \
    int c0=__popc(A), c1=__popc(B), c2=__popc(C), c3=__popc(D); \
    int s0 = c0 ? c0 + ((claimed & 1u) ? 0 : 16) : -1; \
    int s1 = c1 ? c1 + ((claimed & 2u) ? 0 : 16) : -1; \
    int s2 = c2 ? c2 + ((claimed & 4u) ? 0 : 16) : -1; \
    int s3 = c3 ? c3 + ((claimed & 8u) ? 0 : 16) : -1; \
    int bests = s0, bestr = 0; \
    if (s1 > bests) { bests = s1; bestr = 1; } \
    if (s2 > bests) { bests = s2; bestr = 2; } \
    if (s3 > bests) { bests = s3; bestr = 3; } \
    unsigned cur = (bestr==0) ? A : (bestr==1) ? B : (bestr==2) ? C : D; \
    int kk = __ffs(cur) - 1; cur &= cur - 1u; \
    A = (bestr==0) ? cur : A; B = (bestr==1) ? cur : B; \
    C = (bestr==2) ? cur : C; D = (bestr==3) ? cur : D; \
    claimed |= 1u << bestr; \
    const int src = (rowb + J) * 16 + kk; \
    g_cmb[dbase + J*32 + t]      = sidx_s[src]; \
    g_cmb[dbase + J*32 + 16 + t] = swt_s[src]; }
        STEP(0, m00,m01,m02,m03) STEP(1, m10,m11,m12,m13)
        STEP(2, m20,m21,m22,m23) STEP(3, m30,m31,m32,m33)
#undef STEP
    }

    // bias table: slot p*4+j for h = p*128 + w*4 + j
    #pragma unroll
    for (int j = 0; j < 4; j++)
        g_cbias[(l*32 + w)*16 + p*4 + j] = bias[l*NH + qq*4 + j];
}

__device__ __forceinline__ float fast_sigmoid(float z) {
    float t;
    asm("tanh.approx.f32 %0, %1;" : "=f"(t) : "f"(0.5f * z));
    return fmaf(0.5f, t, 0.5f);
}

// ---------------- main fused kernel (R7 hot loop + smem bias) ----------------
__global__ __launch_bounds__(1024, 1)
void ffn_kernel(const float* __restrict__ x,
                float*       __restrict__ out)
{
    extern __shared__ __half2 smem2[];
    __half2* vals2 = smem2;                               // [4096 cols][8 rp], stride 8
    char*    stage = (char*)(smem2 + WSTORE * VST);       // 32 warp-private 2304B blocks + bias

    unsigned int stage_u32 =
        (unsigned int)__cvta_generic_to_shared(stage);

    const int tid  = threadIdx.x;
    const int lane = tid & 31;
    const int warp = tid >> 5;
    const int rp   = lane & 7;          // row-pair 0..7
    const int hsub = lane >> 3;         // 0..3
    const int r0   = blockIdx.x * NR;

    // ---- x tile: (c, pp) mapping -> conflict-free STS ----
    #pragma unroll
    for (int i = tid; i < NRP * NIN; i += 1024) {         // 4096 half2
        int c  = i >> 3;
        int pp = i & 7;
        float a = x[(long)(r0 + 2*pp    ) * NIN + c];
        float b = x[(long)(r0 + 2*pp + 1) * NIN + c];
        vals2[c * VST + pp] = __floats2half2_rn(a, b);
    }

    int width = NIN;
    #pragma unroll 1
    for (int l = 0; l < NL; l++) {
        // ---- warp-private staging of this layer's idx|w + bias (cp.async) ----
        {
            const int4* src = (const int4*)(g_cmb + (size_t)(l*32 + warp) * 512);
            const unsigned int dstbase = stage_u32 + warp * STG_WARP;
            const int a = lane >> 3, b = lane & 7;
            #pragma unroll
            for (int c = 0; c < 4; c++) {
                int r = c*4 + a;
                unsigned int dst = dstbase + r * STG_ROW + b * 16;
                const int4* s = src + (c*32 + lane);
                asm volatile("cp.async.ca.shared.global [%0], [%1], 16;"
                             :: "r"(dst), "l"(s));
            }
            if (lane < 4) {
                unsigned int dstb = stage_u32 + BIAS_OFF + warp * 64 + lane * 16;
                const int4* sb = (const int4*)(g_cbias + (l*32 + warp)*16) + lane;
                asm volatile("cp.async.ca.shared.global [%0], [%1], 16;"
                             :: "r"(dstb), "l"(sb));
            }
            asm volatile("cp.async.commit_group;" ::: "memory");
        }

        __syncthreads();   // previous layer's values visible
        asm volatile("cp.async.wait_group 0;" ::: "memory");
        __syncwarp();      // staged chunks visible warp-wide

        const bool last = (l == NL - 1);
        const char* wblk = stage + warp * STG_WARP;
        const float* bwp = (const float*)(stage + BIAS_OFF + warp * 64);

        #pragma unroll
        for (int p = 0; p < 4; p++) {
            const int h = p * 128 + warp * 4 + hsub;
            const char* rowp = wblk + (p*4 + hsub) * STG_ROW;

            // 4 distinct addresses per warp, disjoint bank quads -> 1 wf each
            const int4*   si = (const int4*)  rowp;
            const float4* sw = (const float4*)(rowp + 64);
            int4   i0 = si[0], i1 = si[1], i2 = si[2], i3 = si[3];
            float4 w0 = sw[0], w1 = sw[1], w2 = sw[2], w3 = sw[3];

            float b0 = bwp[p*4 + hsub];       // broadcast LDS (was in-loop LDG)
            float ax0 = b0,   ay0 = b0;
            float ax1 = 0.0f, ay1 = 0.0f;

            // scheduled gathers: 4 cols with distinct (idx & 3) -> 1 wavefront
#define GATHER0(idx, w) { float2 f = __half22float2(vals2[(idx) * VST + rp]); \
                          ax0 = fmaf(f.x, (w), ax0); ay0 = fmaf(f.y, (w), ay0); }
#define GATHER1(idx, w) { float2 f = __half22float2(vals2[(idx) * VST + rp]); \
                          ax1 = fmaf(f.x, (w), ax1); ay1 = fmaf(f.y, (w), ay1); }
            GATHER0(i0.x, w0.x); GATHER1(i0.y, w0.y);
            GATHER0(i0.z, w0.z); GATHER1(i0.w, w0.w);
            GATHER0(i1.x, w1.x); GATHER1(i1.y, w1.y);
            GATHER0(i1.z, w1.z); GATHER1(i1.w, w1.w);
            GATHER0(i2.x, w2.x); GATHER1(i2.y, w2.y);
            GATHER0(i2.z, w2.z); GATHER1(i2.w, w2.w);
            GATHER0(i3.x, w3.x); GATHER1(i3.y, w3.y);
            GATHER0(i3.z, w3.z); GATHER1(i3.w, w3.w);
#undef GATHER0
#undef GATHER1

            float ox = fast_sigmoid(ax0 + ax1);
            float oy = fast_sigmoid(ay0 + ay1);

            if (!last) {
                // h mod 4 = hsub -> distinct octets x 8 rp -> conflict-free store
                vals2[(width + h) * VST + rp] = __floats2half2_rn(ox, oy);
            } else {
                out[(long)(r0 + 2*rp    ) * NH + h] = ox;
                out[(long)(r0 + 2*rp + 1) * NH + h] = oy;
            }
        }
        width += NH;
    }
}

extern "C" void kernel_launch(void* const* d_in, const int* in_sizes, int n_in,
                              void* d_out, int out_size)
{
    const float* x        = (const float*)d_in[0];   // (8192, 512) f32
    const int*   link_idx = (const int*)d_in[1];     // (8, 512, 16) i32
    const float* weights  = (const float*)d_in[2];   // (8, 512, 16) f32
    const float* bias     = (const float*)d_in[3];   // (8, 512) f32
    float*       out      = (float*)d_out;           // (8192, 512) f32

    cudaFuncSetAttribute(ffn_kernel,
                         cudaFuncAttributeMaxDynamicSharedMemorySize, SMEM_BYTES);

    sched_kernel<<<32, 32>>>(link_idx, weights, bias);
    ffn_kernel<<<NB / NR, 1024, SMEM_BYTES>>>(x, out);
}

// round 11
// speedup vs baseline: 1.1762x; 1.0026x over previous
#include <cuda_runtime.h>
#include <cuda_fp16.h>
#include <cstdint>

// Problem constants
#define NL   8
#define NH   512
#define NK   16
#define NIN  512
#define NB   8192
#define NR   16        // batch rows per block (8 row-pairs, half2 packed)
#define NRP  8
#define WSTORE (NIN + (NL-1)*NH)   // 4096 stored columns
#define VST  8         // column stride in half2 words: col c -> bank octet (c & 3)

#define STG_ROW   144                  // staged row stride bytes (128 data + 16 pad)
#define STG_WARP  (16*STG_ROW)         // 2304 B per warp
#define SMEM_BYTES (WSTORE*VST*4 + 32*STG_WARP)   // 131072 + 73728 = 204800

// combined idx|w, warp-blocked: [l][warp][row(=p*4+j)][16 idx | 16 w]
__device__ __align__(16) int g_cmb[NL*32*512];

// ---------------- scheduling pre-kernel ----------------
// 32 blocks x 32 threads; block = (l = bid>>2, p = bid&3), thread = warp-id w.
// Each thread permutes one h-quad so step t uses 4 columns with pairwise-
// distinct (idx mod 4) -> each ffn gather = 1 smem wavefront.
// All in-loop memory is conflict-free: results go to an SMEM scratch
// (slot-major, stride 33) and are copied out coalesced afterwards.
__global__ void sched_kernel(const int* __restrict__ link_idx,
                             const float* __restrict__ weights)
{
    __shared__ int sidx_s[128*16];
    __shared__ int swt_s [128*16];
    __shared__ int scr   [127*33 + 32];   // [slot 0..127][w 0..31], stride 33

    const int tid = threadIdx.x;                 // 0..31 (= w, warp id in ffn)
    const int bid = blockIdx.x;                  // 0..31
    const int l   = bid >> 2;
    const int p   = bid & 3;

    // stage this block's 128 h-rows of idx and w (coalesced)
    {
        const int base = (l * NH + p * 128) * NK;          // 2048 ints per table
        const int4* gi = (const int4*)(link_idx + base);
        const int4* gw = (const int4*)((const int*)weights + base);
        #pragma unroll
        for (int i = tid; i < 512; i += 32) {
            ((int4*)sidx_s)[i] = gi[i];
            ((int4*)swt_s)[i]  = gw[i];
        }
    }
    __syncthreads();

    const int rowb = tid * 4;                    // local h-row base for this quad

    // per-j residue masks as named registers (no dynamic register indexing)
    unsigned m00=0,m01=0,m02=0,m03=0, m10=0,m11=0,m12=0,m13=0;
    unsigned m20=0,m21=0,m22=0,m23=0, m30=0,m31=0,m32=0,m33=0;
#define BUILD(J, A, B, C, D) { \
    const int* row = sidx_s + (rowb + J) * 16; \
    _Pragma("unroll") for (int k = 0; k < 16; k++) { \
        int rr = row[k] & 3; unsigned bit = 1u << k; \
        A |= (rr == 0) ? bit : 0u; B |= (rr == 1) ? bit : 0u; \
        C |= (rr == 2) ? bit : 0u; D |= (rr == 3) ? bit : 0u; } }
    BUILD(0, m00,m01,m02,m03) BUILD(1, m10,m11,m12,m13)
    BUILD(2, m20,m21,m22,m23) BUILD(3, m30,m31,m32,m33)
#undef BUILD

    for (int t = 0; t < 16; t++) {
        unsigned claimed = 0;
#define STEP(J, A, B, C, D) { \
    int c0=__popc(A), c1=__popc(B), c2=__popc(C), c3=__popc(D); \
    int s0 = c0 ? c0 + ((claimed & 1u) ? 0 : 16) : -1; \
    int s1 = c1 ? c1 + ((claimed & 2u) ? 0 : 16) : -1; \
    int s2 = c2 ? c2 + ((claimed & 4u) ? 0 : 16) : -1; \
    int s3 = c3 ? c3 + ((claimed & 8u) ? 0 : 16) : -1; \
    int bests = s0, bestr = 0; \
    if (s1 > bests) { bests = s1; bestr = 1; } \
    if (s2 > bests) { bests = s2; bestr = 2; } \
    if (s3 > bests) { bests = s3; bestr = 3; } \
    unsigned cur = (bestr==0) ? A : (bestr==1) ? B : (bestr==2) ? C : D; \
    int kk = __ffs(cur) - 1; cur &= cur - 1u; \
    A = (bestr==0) ? cur : A; B = (bestr==1) ? cur : B; \
    C = (bestr==2) ? cur : C; D = (bestr==3) ? cur : D; \
    claimed |= 1u << bestr; \
    const int src = (rowb + J) * 16 + kk; \
    scr[(J*32 + t)      * 33 + tid] = sidx_s[src]; \
    scr[(J*32 + 16 + t) * 33 + tid] = swt_s[src]; }
        STEP(0, m00,m01,m02,m03) STEP(1, m10,m11,m12,m13)
        STEP(2, m20,m21,m22,m23) STEP(3, m30,m31,m32,m33)
#undef STEP
    }
    __syncthreads();

    // coalesced copy-out: quad wq's 128-int block -> g_cmb[(l*32+wq)*512 + p*128]
    #pragma unroll 1
    for (int wq = 0; wq < 32; wq++) {
        int* dst = g_cmb + (l*32 + wq)*512 + p*128;
        #pragma unroll
        for (int k = 0; k < 4; k++) {
            int m = tid + 32*k;
            dst[m] = scr[m*33 + wq];     // LDS stride 33 -> conflict-free; STG coalesced
        }
    }
}

__device__ __forceinline__ float fast_sigmoid(float z) {
    float t;
    asm("tanh.approx.f32 %0, %1;" : "=f"(t) : "f"(0.5f * z));
    return fmaf(0.5f, t, 0.5f);
}

// ---------------- main fused kernel (R9's proven 121us hot loop) ----------------
__global__ __launch_bounds__(1024, 1)
void ffn_kernel(const float* __restrict__ x,
                const float* __restrict__ bias,
                float*       __restrict__ out)
{
    extern __shared__ __half2 smem2[];
    __half2* vals2 = smem2;                               // [4096 cols][8 rp], stride 8
    char*    stage = (char*)(smem2 + WSTORE * VST);       // 32 warp-private 2304B blocks

    unsigned int stage_u32 =
        (unsigned int)__cvta_generic_to_shared(stage);

    const int tid  = threadIdx.x;
    const int lane = tid & 31;
    const int warp = tid >> 5;
    const int rp   = lane & 7;          // row-pair 0..7
    const int hsub = lane >> 3;         // 0..3
    const int r0   = blockIdx.x * NR;

    // ---- x tile: (c, pp) mapping -> conflict-free STS ----
    #pragma unroll
    for (int i = tid; i < NRP * NIN; i += 1024) {         // 4096 half2
        int c  = i >> 3;
        int pp = i & 7;
        float a = x[(long)(r0 + 2*pp    ) * NIN + c];
        float b = x[(long)(r0 + 2*pp + 1) * NIN + c];
        vals2[c * VST + pp] = __floats2half2_rn(a, b);
    }

    int width = NIN;
    #pragma unroll 1
    for (int l = 0; l < NL; l++) {
        // ---- warp-private staging of this layer's combined idx|w (cp.async) ----
        {
            const int4* src = (const int4*)(g_cmb + (size_t)(l*32 + warp) * 512);
            const unsigned int dstbase = stage_u32 + warp * STG_WARP;
            const int a = lane >> 3, b = lane & 7;
            #pragma unroll
            for (int c = 0; c < 4; c++) {
                int r = c*4 + a;
                unsigned int dst = dstbase + r * STG_ROW + b * 16;
                const int4* s = src + (c*32 + lane);
                asm volatile("cp.async.ca.shared.global [%0], [%1], 16;"
                             :: "r"(dst), "l"(s));
            }
            asm volatile("cp.async.commit_group;" ::: "memory");
        }

        __syncthreads();   // previous layer's values visible
        asm volatile("cp.async.wait_group 0;" ::: "memory");
        __syncwarp();      // staged chunks visible warp-wide

        const float* brow = bias + l * NH;
        const bool last = (l == NL - 1);
        const char* wblk = stage + warp * STG_WARP;

        #pragma unroll
        for (int p = 0; p < 4; p++) {
            const int h = p * 128 + warp * 4 + hsub;
            const char* rowp = wblk + (p*4 + hsub) * STG_ROW;

            // 4 distinct addresses per warp, disjoint bank quads -> 1 wf each
            const int4*   si = (const int4*)  rowp;
            const float4* sw = (const float4*)(rowp + 64);
            int4   i0 = si[0], i1 = si[1], i2 = si[2], i3 = si[3];
            float4 w0 = sw[0], w1 = sw[1], w2 = sw[2], w3 = sw[3];

            float b0 = __ldg(brow + h);
            float ax0 = b0,   ay0 = b0;
            float ax1 = 0.0f, ay1 = 0.0f;

            // scheduled gathers: 4 cols with distinct (idx & 3) -> 1 wavefront
#define GATHER0(idx, w) { float2 f = __half22float2(vals2[(idx) * VST + rp]); \
                          ax0 = fmaf(f.x, (w), ax0); ay0 = fmaf(f.y, (w), ay0); }
#define GATHER1(idx, w) { float2 f = __half22float2(vals2[(idx) * VST + rp]); \
                          ax1 = fmaf(f.x, (w), ax1); ay1 = fmaf(f.y, (w), ay1); }
            GATHER0(i0.x, w0.x); GATHER1(i0.y, w0.y);
            GATHER0(i0.z, w0.z); GATHER1(i0.w, w0.w);
            GATHER0(i1.x, w1.x); GATHER1(i1.y, w1.y);
            GATHER0(i1.z, w1.z); GATHER1(i1.w, w1.w);
            GATHER0(i2.x, w2.x); GATHER1(i2.y, w2.y);
            GATHER0(i2.z, w2.z); GATHER1(i2.w, w2.w);
            GATHER0(i3.x, w3.x); GATHER1(i3.y, w3.y);
            GATHER0(i3.z, w3.z); GATHER1(i3.w, w3.w);
#undef GATHER0
#undef GATHER1

            float ox = fast_sigmoid(ax0 + ax1);
            float oy = fast_sigmoid(ay0 + ay1);

            if (!last) {
                // h mod 4 = hsub -> distinct octets x 8 rp -> conflict-free store
                vals2[(width + h) * VST + rp] = __floats2half2_rn(ox, oy);
            } else {
                out[(long)(r0 + 2*rp    ) * NH + h] = ox;
                out[(long)(r0 + 2*rp + 1) * NH + h] = oy;
            }
        }
        width += NH;
    }
}

extern "C" void kernel_launch(void* const* d_in, const int* in_sizes, int n_in,
                              void* d_out, int out_size)
{
    const float* x        = (const float*)d_in[0];   // (8192, 512) f32
    const int*   link_idx = (const int*)d_in[1];     // (8, 512, 16) i32
    const float* weights  = (const float*)d_in[2];   // (8, 512, 16) f32
    const float* bias     = (const float*)d_in[3];   // (8, 512) f32
    float*       out      = (float*)d_out;           // (8192, 512) f32

    cudaFuncSetAttribute(ffn_kernel,
                         cudaFuncAttributeMaxDynamicSharedMemorySize, SMEM_BYTES);

    sched_kernel<<<32, 32>>>(link_idx, weights);
    ffn_kernel<<<NB / NR, 1024, SMEM_BYTES>>>(x, bias, out);
}

// round 12
// speedup vs baseline: 1.2111x; 1.0297x over previous
#include <cuda_runtime.h>
#include <cuda_fp16.h>
#include <cstdint>

// Problem constants
#define NL   8
#define NH   512
#define NK   16
#define NIN  512
#define NB   8192
#define NR   16        // batch rows per block (8 row-pairs, half2 packed)
#define NRP  8
#define WSTORE (NIN + (NL-1)*NH)   // 4096 stored columns (max gathered idx = 4095)
#define VST  8         // column stride in half2 words: col c -> bank octet (c & 3)

// staged row: 16 u16 idx (32B) + 16 f16 w (32B) = 64B data, padded to 96B.
// pass rows p*4+{0..3}: (96*j) mod 128 = {0,96,64,32} -> 4 distinct bank quads.
#define STG_ROW   96
#define STG_WARP  (16*STG_ROW)                 // 1536 B per warp
#define STG_BUF   (32*STG_WARP)                // 49152 B per buffer
#define SMEM_BYTES (WSTORE*VST*4 + 2*STG_BUF)  // 131072 + 98304 = 229376 <= 232448

// packed idx|w, warp-blocked: per (l,warp): 16 rows x 16 u32 (64B rows, contiguous)
// row layout: words 0..7 = idx[2i]|idx[2i+1]<<16 ; words 8..15 = half2(w[2i],w[2i+1])
__device__ __align__(16) unsigned int g_cmb[NL*32*256];

// ---------------- scheduling pre-kernel ----------------
// 32 blocks x 32 threads; block = (l = bid>>2, p = bid&3), thread = ffn warp id.
// Permutes each h-quad's 16 (idx,w) pairs so step t uses 4 columns with
// pairwise-distinct (idx mod 4) -> each ffn gather = 1 smem wavefront.
__global__ void sched_kernel(const int* __restrict__ link_idx,
                             const float* __restrict__ weights)
{
    __shared__ int sidx_s[128*16];
    __shared__ int swt_s [128*16];
    __shared__ unsigned int scr[127*33 + 32];   // [slot 0..127][w 0..31], stride 33

    const int tid = threadIdx.x;                 // 0..31
    const int bid = blockIdx.x;                  // 0..31
    const int l   = bid >> 2;
    const int p   = bid & 3;

    // stage this block's 128 h-rows of idx and w (coalesced)
    {
        const int base = (l * NH + p * 128) * NK;          // 2048 ints per table
        const int4* gi = (const int4*)(link_idx + base);
        const int4* gw = (const int4*)((const int*)weights + base);
        #pragma unroll
        for (int i = tid; i < 512; i += 32) {
            ((int4*)sidx_s)[i] = gi[i];
            ((int4*)swt_s)[i]  = gw[i];
        }
    }
    __syncthreads();

    const int rowb = tid * 4;                    // local h-row base for this quad

    unsigned m00=0,m01=0,m02=0,m03=0, m10=0,m11=0,m12=0,m13=0;
    unsigned m20=0,m21=0,m22=0,m23=0, m30=0,m31=0,m32=0,m33=0;
#define BUILD(J, A, B, C, D) { \
    const int* row = sidx_s + (rowb + J) * 16; \
    _Pragma("unroll") for (int k = 0; k < 16; k++) { \
        int rr = row[k] & 3; unsigned bit = 1u << k; \
        A |= (rr == 0) ? bit : 0u; B |= (rr == 1) ? bit : 0u; \
        C |= (rr == 2) ? bit : 0u; D |= (rr == 3) ? bit : 0u; } }
    BUILD(0, m00,m01,m02,m03) BUILD(1, m10,m11,m12,m13)
    BUILD(2, m20,m21,m22,m23) BUILD(3, m30,m31,m32,m33)
#undef BUILD

    for (int t = 0; t < 16; t++) {
        unsigned claimed = 0;
#define STEP(J, A, B, C, D) { \
    int c0=__popc(A), c1=__popc(B), c2=__popc(C), c3=__popc(D); \
    int s0 = c0 ? c0 + ((claimed & 1u) ? 0 : 16) : -1; \
    int s1 = c1 ? c1 + ((claimed & 2u) ? 0 : 16) : -1; \
    int s2 = c2 ? c2 + ((claimed & 4u) ? 0 : 16) : -1; \
    int s3 = c3 ? c3 + ((claimed & 8u) ? 0 : 16) : -1; \
    int bests = s0, bestr = 0; \
    if (s1 > bests) { bests = s1; bestr = 1; } \
    if (s2 > bests) { bests = s2; bestr = 2; } \
    if (s3 > bests) { bests = s3; bestr = 3; } \
    unsigned cur = (bestr==0) ? A : (bestr==1) ? B : (bestr==2) ? C : D; \
    int kk = __ffs(cur) - 1; cur &= cur - 1u; \
    A = (bestr==0) ? cur : A; B = (bestr==1) ? cur : B; \
    C = (bestr==2) ? cur : C; D = (bestr==3) ? cur : D; \
    claimed |= 1u << bestr; \
    const int src = (rowb + J) * 16 + kk; \
    scr[(J*32 + t)      * 33 + tid] = (unsigned)sidx_s[src]; \
    scr[(J*32 + 16 + t) * 33 + tid] = (unsigned)swt_s[src]; }
        STEP(0, m00,m01,m02,m03) STEP(1, m10,m11,m12,m13)
        STEP(2, m20,m21,m22,m23) STEP(3, m30,m31,m32,m33)
#undef STEP
    }
    __syncthreads();

    // coalesced packed copy-out: quad wq -> g_cmb[(l*32+wq)*256 + p*64 .. +63]
    #pragma unroll 1
    for (int wq = 0; wq < 32; wq++) {
        unsigned int* dst = g_cmb + (l*32 + wq)*256 + p*64;
        #pragma unroll
        for (int r = 0; r < 2; r++) {
            int wi  = r*32 + tid;          // word 0..63
            int row = wi >> 4;             // J
            int pos = wi & 15;
            unsigned val;
            if (pos < 8) {                 // idx pair for t = 2*pos, 2*pos+1
                unsigned a = scr[(row*32 + 2*pos    )*33 + wq];
                unsigned b = scr[(row*32 + 2*pos + 1)*33 + wq];
                val = (a & 0xFFFFu) | (b << 16);
            } else {                       // weight pair as half2
                int k = pos - 8;
                unsigned a = scr[(row*32 + 16 + 2*k    )*33 + wq];
                unsigned b = scr[(row*32 + 16 + 2*k + 1)*33 + wq];
                __half ha = __float2half_rn(__uint_as_float(a));
                __half hb = __float2half_rn(__uint_as_float(b));
                val = (unsigned)__half_as_ushort(ha)
                    | ((unsigned)__half_as_ushort(hb) << 16);
            }
            dst[wi] = val;                 // coalesced STG.32
        }
    }
}

__device__ __forceinline__ float fast_sigmoid(float z) {
    float t;
    asm("tanh.approx.f32 %0, %1;" : "=f"(t) : "f"(0.5f * z));
    return fmaf(0.5f, t, 0.5f);
}

// ---------------- main fused kernel (double-buffered staging) ----------------
__global__ __launch_bounds__(1024, 1)
void ffn_kernel(const float* __restrict__ x,
                const float* __restrict__ bias,
                float*       __restrict__ out)
{
    extern __shared__ __half2 smem2[];
    __half2* vals2 = smem2;                               // [4096 cols][8 rp], stride 8
    char*    stage = (char*)(smem2 + WSTORE * VST);       // 2 x 48KB staging buffers

    const unsigned int stage_u32 =
        (unsigned int)__cvta_generic_to_shared(stage);

    const int tid  = threadIdx.x;
    const int lane = tid & 31;
    const int warp = tid >> 5;
    const int rp   = lane & 7;          // row-pair 0..7
    const int hsub = lane >> 3;         // 0..3
    const int r0   = blockIdx.x * NR;

    // warp-private prefetch of one layer's packed idx|w (1024B -> 64 16B chunks)
#define PREFETCH(L, BUF) { \
    const int4* src = (const int4*)(g_cmb + (size_t)((L)*32 + warp) * 256); \
    const unsigned int dstbase = stage_u32 + (BUF)*STG_BUF + warp*STG_WARP; \
    _Pragma("unroll") for (int c = 0; c < 2; c++) { \
        int c2 = c*32 + lane; \
        unsigned int dst = dstbase + (c2 >> 2) * STG_ROW + (c2 & 3) * 16; \
        asm volatile("cp.async.ca.shared.global [%0], [%1], 16;" \
                     :: "r"(dst), "l"(src + c2)); } \
    asm volatile("cp.async.commit_group;" ::: "memory"); }

    PREFETCH(0, 0)

    // ---- x tile: (c, pp) mapping -> conflict-free STS ----
    #pragma unroll
    for (int i = tid; i < NRP * NIN; i += 1024) {         // 4096 half2
        int c  = i >> 3;
        int pp = i & 7;
        float a = x[(long)(r0 + 2*pp    ) * NIN + c];
        float b = x[(long)(r0 + 2*pp + 1) * NIN + c];
        vals2[c * VST + pp] = __floats2half2_rn(a, b);
    }

    int width = NIN;
    #pragma unroll 1
    for (int l = 0; l < NL; l++) {
        const int buf = l & 1;
        if (l < NL - 1) {
            PREFETCH(l + 1, buf ^ 1)                       // hide behind barrier+compute
            __syncthreads();                               // prev layer's values visible
            asm volatile("cp.async.wait_group 1;" ::: "memory");  // this layer's data done
        } else {
            __syncthreads();
            asm volatile("cp.async.wait_group 0;" ::: "memory");
        }
        __syncwarp();

        const float* brow = bias + l * NH;
        const bool last = (l == NL - 1);
        const char* wblk = stage + buf*STG_BUF + warp*STG_WARP;

        #pragma unroll
        for (int p = 0; p < 4; p++) {
            const int h = p * 128 + warp * 4 + hsub;
            const char* rowp = wblk + (p*4 + hsub) * STG_ROW;

            // 2 idx LDS.128 + 2 w LDS.128; 4 distinct bank quads across hsub
            int4 ia = *(const int4*)(rowp);        // idx pairs t0..7
            int4 ib = *(const int4*)(rowp + 16);   // idx pairs t8..15
            int4 wa = *(const int4*)(rowp + 32);   // w half2 t0..7
            int4 wb = *(const int4*)(rowp + 48);   // w half2 t8..15

            float2 wf0 = __half22float2(*(const __half2*)&wa.x);
            float2 wf1 = __half22float2(*(const __half2*)&wa.y);
            float2 wf2 = __half22float2(*(const __half2*)&wa.z);
            float2 wf3 = __half22float2(*(const __half2*)&wa.w);
            float2 wf4 = __half22float2(*(const __half2*)&wb.x);
            float2 wf5 = __half22float2(*(const __half2*)&wb.y);
            float2 wf6 = __half22float2(*(const __half2*)&wb.z);
            float2 wf7 = __half22float2(*(const __half2*)&wb.w);

            float b0 = __ldg(brow + h);
            float ax0 = b0,   ay0 = b0;
            float ax1 = 0.0f, ay1 = 0.0f;

            // scheduled gathers: 4 cols with distinct (idx & 3) -> 1 wavefront
#define G0(ii, ww) { float2 f = __half22float2(vals2[(ii) * VST + rp]); \
                     ax0 = fmaf(f.x, (ww), ax0); ay0 = fmaf(f.y, (ww), ay0); }
#define G1(ii, ww) { float2 f = __half22float2(vals2[(ii) * VST + rp]); \
                     ax1 = fmaf(f.x, (ww), ax1); ay1 = fmaf(f.y, (ww), ay1); }
            G0(ia.x & 0xFFFF, wf0.x); G1(ia.x >> 16, wf0.y);
            G0(ia.y & 0xFFFF, wf1.x); G1(ia.y >> 16, wf1.y);
            G0(ia.z & 0xFFFF, wf2.x); G1(ia.z >> 16, wf2.y);
            G0(ia.w & 0xFFFF, wf3.x); G1(ia.w >> 16, wf3.y);
            G0(ib.x & 0xFFFF, wf4.x); G1(ib.x >> 16, wf4.y);
            G0(ib.y & 0xFFFF, wf5.x); G1(ib.y >> 16, wf5.y);
            G0(ib.z & 0xFFFF, wf6.x); G1(ib.z >> 16, wf6.y);
            G0(ib.w & 0xFFFF, wf7.x); G1(ib.w >> 16, wf7.y);
#undef G0
#undef G1

            float ox = fast_sigmoid(ax0 + ax1);
            float oy = fast_sigmoid(ay0 + ay1);

            if (!last) {
                // h mod 4 = hsub -> distinct octets x 8 rp -> conflict-free store
                vals2[(width + h) * VST + rp] = __floats2half2_rn(ox, oy);
            } else {
                out[(long)(r0 + 2*rp    ) * NH + h] = ox;
                out[(long)(r0 + 2*rp + 1) * NH + h] = oy;
            }
        }
        width += NH;
    }
#undef PREFETCH
}

extern "C" void kernel_launch(void* const* d_in, const int* in_sizes, int n_in,
                              void* d_out, int out_size)
{
    const float* x        = (const float*)d_in[0];   // (8192, 512) f32
    const int*   link_idx = (const int*)d_in[1];     // (8, 512, 16) i32
    const float* weights  = (const float*)d_in[2];   // (8, 512, 16) f32
    const float* bias     = (const float*)d_in[3];   // (8, 512) f32
    float*       out      = (float*)d_out;           // (8192, 512) f32

    cudaFuncSetAttribute(ffn_kernel,
                         cudaFuncAttributeMaxDynamicSharedMemorySize, SMEM_BYTES);

    sched_kernel<<<32, 32>>>(link_idx, weights);
    ffn_kernel<<<NB / NR, 1024, SMEM_BYTES>>>(x, bias, out);
}

// round 13
// speedup vs baseline: 1.2138x; 1.0022x over previous
#include <cuda_runtime.h>
#include <cuda_fp16.h>
#include <cstdint>

// Problem constants
#define NL   8
#define NH   512
#define NK   16
#define NIN  512
#define NB   8192
#define NR   16        // batch rows per block (8 row-pairs, half2 packed)
#define NRP  8
#define WSTORE (NIN + (NL-1)*NH)   // 4096 stored columns (max gathered idx = 4095)
#define VST  8         // column stride in half2 words: col c -> bank octet (c & 3)

// staged row: 16 u32 pre-scaled byte offsets (64B) + 16 f16 weights (32B) = 96B.
// rows at j*96 mod 128 = {0,96,64,32} -> 4 distinct bank quads across hsub.
#define STG_ROW   96
#define STG_WARP  (16*STG_ROW)                 // 1536 B per warp (contiguous)
#define STG_BUF   (32*STG_WARP)                // 49152 B per buffer
#define SMEM_BYTES (WSTORE*VST*4 + 2*STG_BUF)  // 131072 + 98304 = 229376 <= 232448

// packed table, warp-blocked: per (l,warp): 16 rows x 24 u32 (96B rows, contiguous)
// row layout: words 0..15 = idx*32 (byte offsets); words 16..23 = half2(w[2t],w[2t+1])
__device__ __align__(16) unsigned int g_cmb[NL*32*384];

// ---------------- scheduling pre-kernel ----------------
// 32 blocks x 32 threads; block = (l = bid>>2, p = bid&3), thread = ffn warp id.
// Permutes each h-quad's 16 (idx,w) pairs so step t uses 4 columns with
// pairwise-distinct (idx mod 4) -> each ffn gather = 1 smem wavefront.
__global__ void sched_kernel(const int* __restrict__ link_idx,
                             const float* __restrict__ weights)
{
    __shared__ int sidx_s[128*16];
    __shared__ int swt_s [128*16];
    __shared__ unsigned int scr[127*33 + 32];   // [slot 0..127][w 0..31], stride 33

    const int tid = threadIdx.x;                 // 0..31
    const int bid = blockIdx.x;                  // 0..31
    const int l   = bid >> 2;
    const int p   = bid & 3;

    // stage this block's 128 h-rows of idx and w (coalesced)
    {
        const int base = (l * NH + p * 128) * NK;          // 2048 ints per table
        const int4* gi = (const int4*)(link_idx + base);
        const int4* gw = (const int4*)((const int*)weights + base);
        #pragma unroll
        for (int i = tid; i < 512; i += 32) {
            ((int4*)sidx_s)[i] = gi[i];
            ((int4*)swt_s)[i]  = gw[i];
        }
    }
    __syncthreads();

    const int rowb = tid * 4;                    // local h-row base for this quad

    unsigned m00=0,m01=0,m02=0,m03=0, m10=0,m11=0,m12=0,m13=0;
    unsigned m20=0,m21=0,m22=0,m23=0, m30=0,m31=0,m32=0,m33=0;
#define BUILD(J, A, B, C, D) { \
    const int* row = sidx_s + (rowb + J) * 16; \
    _Pragma("unroll") for (int k = 0; k < 16; k++) { \
        int rr = row[k] & 3; unsigned bit = 1u << k; \
        A |= (rr == 0) ? bit : 0u; B |= (rr == 1) ? bit : 0u; \
        C |= (rr == 2) ? bit : 0u; D |= (rr == 3) ? bit : 0u; } }
    BUILD(0, m00,m01,m02,m03) BUILD(1, m10,m11,m12,m13)
    BUILD(2, m20,m21,m22,m23) BUILD(3, m30,m31,m32,m33)
#undef BUILD

    for (int t = 0; t < 16; t++) {
        unsigned claimed = 0;
#define STEP(J, A, B, C, D) { \
    int c0=__popc(A), c1=__popc(B), c2=__popc(C), c3=__popc(D); \
    int s0 = c0 ? c0 + ((claimed & 1u) ? 0 : 16) : -1; \
    int s1 = c1 ? c1 + ((claimed & 2u) ? 0 : 16) : -1; \
    int s2 = c2 ? c2 + ((claimed & 4u) ? 0 : 16) : -1; \
    int s3 = c3 ? c3 + ((claimed & 8u) ? 0 : 16) : -1; \
    int bests = s0, bestr = 0; \
    if (s1 > bests) { bests = s1; bestr = 1; } \
    if (s2 > bests) { bests = s2; bestr = 2; } \
    if (s3 > bests) { bests = s3; bestr = 3; } \
    unsigned cur = (bestr==0) ? A : (bestr==1) ? B : (bestr==2) ? C : D; \
    int kk = __ffs(cur) - 1; cur &= cur - 1u; \
    A = (bestr==0) ? cur : A; B = (bestr==1) ? cur : B; \
    C = (bestr==2) ? cur : C; D = (bestr==3) ? cur : D; \
    claimed |= 1u << bestr; \
    const int src = (rowb + J) * 16 + kk; \
    scr[(J*32 + t)      * 33 + tid] = (unsigned)sidx_s[src]; \
    scr[(J*32 + 16 + t) * 33 + tid] = (unsigned)swt_s[src]; }
        STEP(0, m00,m01,m02,m03) STEP(1, m10,m11,m12,m13)
        STEP(2, m20,m21,m22,m23) STEP(3, m30,m31,m32,m33)
#undef STEP
    }
    __syncthreads();

    // coalesced packed copy-out: quad wq -> g_cmb[(l*32+wq)*384 + p*96 .. +95]
    #pragma unroll 1
    for (int wq = 0; wq < 32; wq++) {
        unsigned int* dst = g_cmb + (l*32 + wq)*384 + p*96;
        #pragma unroll
        for (int r = 0; r < 3; r++) {
            int wi  = r*32 + tid;          // word 0..95
            int row = wi / 24;             // J (0..3)
            int pos = wi % 24;
            unsigned val;
            if (pos < 16) {                // pre-scaled byte offset for step t=pos
                val = scr[(row*32 + pos)*33 + wq] << 5;     // idx * 32
            } else {                       // weight pair (t=2k, 2k+1) as half2
                int k = pos - 16;
                unsigned a = scr[(row*32 + 16 + 2*k    )*33 + wq];
                unsigned b = scr[(row*32 + 16 + 2*k + 1)*33 + wq];
                __half ha = __float2half_rn(__uint_as_float(a));
                __half hb = __float2half_rn(__uint_as_float(b));
                val = (unsigned)__half_as_ushort(ha)
                    | ((unsigned)__half_as_ushort(hb) << 16);
            }
            dst[wi] = val;                 // coalesced STG.32
        }
    }
}

__device__ __forceinline__ float fast_sigmoid(float z) {
    float t;
    asm("tanh.approx.f32 %0, %1;" : "=f"(t) : "f"(0.5f * z));
    return fmaf(0.5f, t, 0.5f);
}

// ---------------- main fused kernel (fp16 sub-chain accumulation) ----------------
__global__ __launch_bounds__(1024, 1)
void ffn_kernel(const float* __restrict__ x,
                const float* __restrict__ bias,
                float*       __restrict__ out)
{
    extern __shared__ __half2 smem2[];
    __half2* vals2 = smem2;                               // [4096 cols][8 rp], stride 8
    char*    stage = (char*)(smem2 + WSTORE * VST);       // 2 x 48KB staging buffers

    const unsigned int stage_u32 =
        (unsigned int)__cvta_generic_to_shared(stage);

    const int tid  = threadIdx.x;
    const int lane = tid & 31;
    const int warp = tid >> 5;
    const int rp   = lane & 7;          // row-pair 0..7
    const int hsub = lane >> 3;         // 0..3
    const int r0   = blockIdx.x * NR;

    // per-thread value base: gathers read *(half2*)(vbase + staged_byte_offset)
    const char* vbase = (const char*)vals2 + rp * 4;

    // warp-private prefetch of one layer's packed table (1536B contiguous)
#define PREFETCH(L, BUF) { \
    const char* src = (const char*)(g_cmb + (size_t)((L)*32 + warp) * 384); \
    const unsigned int dstbase = stage_u32 + (BUF)*STG_BUF + warp*STG_WARP; \
    _Pragma("unroll") for (int c = 0; c < 3; c++) { \
        int c2 = (c*32 + lane) * 16; \
        asm volatile("cp.async.ca.shared.global [%0], [%1], 16;" \
                     :: "r"(dstbase + c2), "l"(src + c2)); } \
    asm volatile("cp.async.commit_group;" ::: "memory"); }

    PREFETCH(0, 0)

    // ---- x tile: (c, pp) mapping -> conflict-free STS ----
    #pragma unroll
    for (int i = tid; i < NRP * NIN; i += 1024) {         // 4096 half2
        int c  = i >> 3;
        int pp = i & 7;
        float a = x[(long)(r0 + 2*pp    ) * NIN + c];
        float b = x[(long)(r0 + 2*pp + 1) * NIN + c];
        vals2[c * VST + pp] = __floats2half2_rn(a, b);
    }

    int width = NIN;
    #pragma unroll 1
    for (int l = 0; l < NL; l++) {
        const int buf = l & 1;
        if (l < NL - 1) {
            PREFETCH(l + 1, buf ^ 1)                       // hide behind barrier+compute
            __syncthreads();                               // prev layer's values visible
            asm volatile("cp.async.wait_group 1;" ::: "memory");
        } else {
            __syncthreads();
            asm volatile("cp.async.wait_group 0;" ::: "memory");
        }
        __syncwarp();

        const float* brow = bias + l * NH;
        const bool last = (l == NL - 1);
        const char* wblk = stage + buf*STG_BUF + warp*STG_WARP;

        #pragma unroll
        for (int p = 0; p < 4; p++) {
            const int h = p * 128 + warp * 4 + hsub;
            const char* rowp = wblk + (p*4 + hsub) * STG_ROW;

            // 4 idx LDS.128 + 2 w LDS.128; hsub rows hit 4 distinct bank quads
            uint4 ia = *(const uint4*)(rowp);        // byte offsets t0..3
            uint4 ib = *(const uint4*)(rowp + 16);   // t4..7
            uint4 ic = *(const uint4*)(rowp + 32);   // t8..11
            uint4 id = *(const uint4*)(rowp + 48);   // t12..15
            uint4 wa = *(const uint4*)(rowp + 64);   // w halves t0..7
            uint4 wb = *(const uint4*)(rowp + 80);   // w halves t8..15

            float ax = 0.0f, ay = 0.0f;

            // sub-chain of 4 fp16 HFMA2 steps, flushed into fp32 (keeps rounding small)
#define LDV(off) (*(const __half2*)(vbase + (off)))
#define SUBCHAIN(iv, wp0, wp1) { \
    __half2 hw0 = *(const __half2*)&(wp0); \
    __half2 hw1 = *(const __half2*)&(wp1); \
    __half2 hacc = __hmul2(LDV((iv).x), __half2half2(__low2half(hw0))); \
    hacc = __hfma2(LDV((iv).y), __half2half2(__high2half(hw0)), hacc); \
    hacc = __hfma2(LDV((iv).z), __half2half2(__low2half(hw1)),  hacc); \
    hacc = __hfma2(LDV((iv).w), __half2half2(__high2half(hw1)), hacc); \
    float2 f = __half22float2(hacc); ax += f.x; ay += f.y; }

            SUBCHAIN(ia, wa.x, wa.y)
            SUBCHAIN(ib, wa.z, wa.w)
            SUBCHAIN(ic, wb.x, wb.y)
            SUBCHAIN(id, wb.z, wb.w)
#undef SUBCHAIN
#undef LDV

            float b0 = __ldg(brow + h);
            float ox = fast_sigmoid(ax + b0);
            float oy = fast_sigmoid(ay + b0);

            if (!last) {
                // h mod 4 = hsub -> distinct octets x 8 rp -> conflict-free store
                vals2[(width + h) * VST + rp] = __floats2half2_rn(ox, oy);
            } else {
                out[(long)(r0 + 2*rp    ) * NH + h] = ox;
                out[(long)(r0 + 2*rp + 1) * NH + h] = oy;
            }
        }
        width += NH;
    }
#undef PREFETCH
}

extern "C" void kernel_launch(void* const* d_in, const int* in_sizes, int n_in,
                              void* d_out, int out_size)
{
    const float* x        = (const float*)d_in[0];   // (8192, 512) f32
    const int*   link_idx = (const int*)d_in[1];     // (8, 512, 16) i32
    const float* weights  = (const float*)d_in[2];   // (8, 512, 16) f32
    const float* bias     = (const float*)d_in[3];   // (8, 512) f32
    float*       out      = (float*)d_out;           // (8192, 512) f32

    cudaFuncSetAttribute(ffn_kernel,
                         cudaFuncAttributeMaxDynamicSharedMemorySize, SMEM_BYTES);

    sched_kernel<<<32, 32>>>(link_idx, weights);
    ffn_kernel<<<NB / NR, 1024, SMEM_BYTES>>>(x, bias, out);
}